// round 8
// baseline (speedup 1.0000x reference)
#include <cuda_runtime.h>
#include <cuda_fp16.h>

// ---------------------------------------------------------------------------
// BlocCircLinear via mma.sync m16n8k16 (f16 in / f32 acc), compute_103-safe.
//   D[b=32, 8192] = X[32, 8192] @ W^T,  W block-circulant from blocks[512][16][16].
// R8: R7 fused-staging design with the x-chunk K-offset bug fixed
//   (ks*512 -> ks*256 float4: CTA K range is 1024 floats = 256 float4).
//   2 kernels: bc_mma (128 CTAs x 512 thr, fused f32->f16 staging) + reduce.
// ---------------------------------------------------------------------------

#define BATCH   32
#define NBLK    512
#define DIM     8192
#define NTILES  16        // 8192 / 512 output cols
#define KSPLIT  8         // K split across CTAs -> 1024 per CTA
#define JSTEPS2 32        // 512 k per half / 16
#define THREADS 512

#define XS_STR   1032                       // halves per x row (1024 + 8 pad)
#define BLK_N    95                         // blocks staged per CTA
#define PAD_LO   512                        // underflow pad (B prefetch d = -1)
#define PAD_HI   1024                       // overflow pad (A prefetch @ last j)
#define OFF_BLK  PAD_LO
#define OFF_XS   (PAD_LO + BLK_N * 512)     // 512 + 48640
#define SMEM_TOT (OFF_XS + BATCH * XS_STR * 2 + PAD_HI)   // 116224

__device__ float g_part[KSPLIT][BATCH * DIM];   // partials [8][32][8192]

static __device__ __forceinline__ unsigned swzb(unsigned off) {
    return off ^ ((off >> 3) & 0x70);
}
static __device__ __forceinline__ unsigned smem_u32(const void* p) {
    return (unsigned)__cvta_generic_to_shared(p);
}
static __device__ __forceinline__ void ldsm4(unsigned* r, unsigned addr) {
    asm volatile("ldmatrix.sync.aligned.m8n8.x4.shared.b16 {%0,%1,%2,%3}, [%4];"
                 : "=r"(r[0]), "=r"(r[1]), "=r"(r[2]), "=r"(r[3]) : "r"(addr));
}
static __device__ __forceinline__ void mma16816(float* c, const unsigned* a,
                                                unsigned b0, unsigned b1) {
    asm volatile(
        "mma.sync.aligned.m16n8k16.row.col.f32.f16.f16.f32 "
        "{%0,%1,%2,%3}, {%4,%5,%6,%7}, {%8,%9}, {%0,%1,%2,%3};"
        : "+f"(c[0]), "+f"(c[1]), "+f"(c[2]), "+f"(c[3])
        : "r"(a[0]), "r"(a[1]), "r"(a[2]), "r"(a[3]), "r"(b0), "r"(b1));
}
static __device__ __forceinline__ uint4 cvt8(float4 a, float4 b) {
    __half2 h0 = __float22half2_rn(make_float2(a.x, a.y));
    __half2 h1 = __float22half2_rn(make_float2(a.z, a.w));
    __half2 h2 = __float22half2_rn(make_float2(b.x, b.y));
    __half2 h3 = __float22half2_rn(make_float2(b.z, b.w));
    uint4 o;
    o.x = *reinterpret_cast<unsigned*>(&h0);
    o.y = *reinterpret_cast<unsigned*>(&h1);
    o.z = *reinterpret_cast<unsigned*>(&h2);
    o.w = *reinterpret_cast<unsigned*>(&h3);
    return o;
}

// ---------------------------------------------------------------------------
// Kernel 1: block-circulant GEMM with fused f32->f16 staging.
// grid = NTILES * KSPLIT = 128 CTAs x 512 threads.
// ---------------------------------------------------------------------------
extern __shared__ __align__(1024) char smem[];

__global__ void __launch_bounds__(THREADS, 1) bc_mma_kernel(
    const float* __restrict__ x32, const float* __restrict__ blk32)
{
    const int tid  = threadIdx.x;
    const int wid  = tid >> 5;
    const int lane = tid & 31;
    const int grp  = wid & 7;                 // col-group 0..7
    const int kh   = wid >> 3;                // k-half 0/1
    const int T    = blockIdx.x & (NTILES - 1);
    const int ks   = blockIdx.x >> 4;
    const int smin = (T * 32 - ks * 64 - 63) & (NBLK - 1);

    char*   blk = smem + OFF_BLK;
    char*   xsb = smem + OFF_XS;

    // ---- stage + convert: x chunk (32 x 1024 f32) and 95 blocks ----
    {
        const float4* xf = reinterpret_cast<const float4*>(x32);
#pragma unroll
        for (int i = tid; i < 4096; i += THREADS) {   // 16B-half chunks
            int row = i >> 7, cc = i & 127;
            // row stride 8192 floats = 2048 float4; CTA K range 1024 floats
            // = 256 float4 -> offset ks*256 (R7 bug: was ks*512).
            const float4* p = xf + row * 2048 + ks * 256 + cc * 2;
            float4 a = p[0], b = p[1];
            *reinterpret_cast<uint4*>(xsb + row * (XS_STR * 2) + cc * 16) =
                cvt8(a, b);
        }
        const float4* bf = reinterpret_cast<const float4*>(blk32);
#pragma unroll
        for (int i = tid; i < BLK_N * 32; i += THREADS) {
            int d = i >> 5, w = i & 31;
            int s = (smin + d) & (NBLK - 1);
            const float4* p = bf + s * 64 + w * 2;
            float4 a = p[0], b = p[1];
            *reinterpret_cast<uint4*>(blk + d * 512 + swzb(w * 16)) =
                cvt8(a, b);
        }
        __syncthreads();
    }

    // ---- lane-invariant ldmatrix addresses ----
    const int a0 = grp * 4;                   // warp's first block-col
    unsigned arow = (unsigned)(lane & 15);
    unsigned kadd = (unsigned)((lane >> 4) * 8);
    unsigned aA0 = smem_u32(xsb) + arow * (XS_STR * 2) + (unsigned)(kh * 1024)
                 + kadd * 2;
    unsigned aA1 = aA0 + 16 * (XS_STR * 2);
    unsigned pr   = (unsigned)(((lane >> 4) & 1) * 8 + (lane & 7));
    unsigned koff = (unsigned)(((lane >> 3) & 1) * 16);
    unsigned bl   = swzb(pr * 32 + koff);
    unsigned bbase = smem_u32(blk) + bl;
    const int d0 = a0 + 63 - kh * 32;         // block window start for this half

    float acc[2][8][4] = {};

    // ---- preload j=0 fragments ----
    unsigned A0[4], A1[4], Bf[4][4];
    ldsm4(A0, aA0);
    ldsm4(A1, aA1);
#pragma unroll
    for (int r = 0; r < 4; ++r)
        ldsm4(Bf[r], bbase + (unsigned)((d0 + r) * 512));
    unsigned bPre = bbase + (unsigned)((d0 - 1) * 512);   // next-step new frag

#pragma unroll 4
    for (int j = 0; j < JSTEPS2; ++j) {
        // prefetch next step (overreads land in smem pads; values unused)
        unsigned An0[4], An1[4], Bn[4];
        ldsm4(An0, aA0 + 32);
        ldsm4(An1, aA1 + 32);
        ldsm4(Bn, bPre);

        // 16 MMAs on current fragments
#pragma unroll
        for (int r = 0; r < 4; ++r) {
            mma16816(acc[0][2 * r],     A0, Bf[r][0], Bf[r][1]);
            mma16816(acc[1][2 * r],     A1, Bf[r][0], Bf[r][1]);
            mma16816(acc[0][2 * r + 1], A0, Bf[r][2], Bf[r][3]);
            mma16816(acc[1][2 * r + 1], A1, Bf[r][2], Bf[r][3]);
        }

        // rotate: window shifts by one block per k-step (circulant)
#pragma unroll
        for (int t = 0; t < 4; ++t) {
            Bf[3][t] = Bf[2][t];
            Bf[2][t] = Bf[1][t];
            Bf[1][t] = Bf[0][t];
            Bf[0][t] = Bn[t];
            A0[t] = An0[t];
            A1[t] = An1[t];
        }
        aA0 += 32; aA1 += 32;
        bPre -= 512;
    }

    // ---- combine k-halves in smem (conflict-free 16B-interleaved layout) ----
    __syncthreads();                          // everyone done reading staged smem
    if (kh == 1) {
#pragma unroll
        for (int m = 0; m < 2; ++m)
#pragma unroll
            for (int nf = 0; nf < 8; ++nf) {
                int rr = m * 8 + nf;
                *reinterpret_cast<float4*>(
                    smem + (rr * 8 + grp) * 512 + lane * 16) =
                    make_float4(acc[m][nf][0], acc[m][nf][1],
                                acc[m][nf][2], acc[m][nf][3]);
            }
    }
    __syncthreads();

    // ---- epilogue: warps 0-7 add other half and store f32 partials ----
    if (kh == 0) {
        const int q  = lane & 3;
        const int rw = lane >> 2;
        float* part = g_part[ks];
#pragma unroll
        for (int m = 0; m < 2; ++m) {
#pragma unroll
            for (int nf = 0; nf < 8; ++nf) {
                int rr = m * 8 + nf;
                float4 o = *reinterpret_cast<float4*>(
                    smem + (rr * 8 + grp) * 512 + lane * 16);
                int col = T * 512 + (a0 + (nf >> 1)) * 16 + (nf & 1) * 8 + q * 2;
                int b0  = m * 16 + rw;
                *reinterpret_cast<float2*>(&part[b0 * DIM + col]) =
                    make_float2(acc[m][nf][0] + o.x, acc[m][nf][1] + o.y);
                *reinterpret_cast<float2*>(&part[(b0 + 8) * DIM + col]) =
                    make_float2(acc[m][nf][2] + o.z, acc[m][nf][3] + o.w);
            }
        }
    }
}

// ---------------------------------------------------------------------------
// Kernel 2: reduce the 8 K-split partials (float4, L2-resident).
// ---------------------------------------------------------------------------
__global__ void __launch_bounds__(256) reduce_kernel(float* __restrict__ out)
{
    int i = blockIdx.x * 256 + threadIdx.x;       // 65536 threads, float4 each
    float4 v = reinterpret_cast<const float4*>(g_part[0])[i];
#pragma unroll
    for (int ksp = 1; ksp < KSPLIT; ++ksp) {
        float4 p = reinterpret_cast<const float4*>(g_part[ksp])[i];
        v.x += p.x; v.y += p.y; v.z += p.z; v.w += p.w;
    }
    reinterpret_cast<float4*>(out)[i] = v;
}

// ---------------------------------------------------------------------------
extern "C" void kernel_launch(void* const* d_in, const int* in_sizes, int n_in,
                              void* d_out, int out_size)
{
    const float* x   = (const float*)d_in[0];
    const float* blk = (const float*)d_in[1];
    float* out = (float*)d_out;

    cudaFuncSetAttribute(bc_mma_kernel,
                         cudaFuncAttributeMaxDynamicSharedMemorySize, SMEM_TOT);

    bc_mma_kernel<<<NTILES * KSPLIT, THREADS, SMEM_TOT>>>(x, blk);
    reduce_kernel<<<256, 256>>>(out);
}